// round 17
// baseline (speedup 1.0000x reference)
#include <cuda_runtime.h>
#include <cstdint>

typedef unsigned long long ull;

#define N_OBJ   4096
#define OBJ_DIM 1024
#define N_PAIRS 65536

// Scratch (device globals: no allocation allowed). 16B-aligned for float4 access.
// g_Mp: EIGHT j-partials of M = W2 @ W1, layout [jt][c16][k] (k in 0..1023).
// c16<8: M[c][k] (sub half), c16>=8: M[c-8][1024+k] (obj half).
// Exclusive writes -> no atomics, no zero-init. g_M: reduced M (by kR).
__device__ __align__(16) float g_Mp[8 * 16 * 1024];   // 512 KB
__device__ __align__(16) float g_M[16 * 1024];        // 64 KB
__device__ __align__(16) float g_cvec[8];             // W2@b1 + b2
__device__ __align__(16) float g_P[N_OBJ * 16];       // per-object projections
__device__ int g_fmt;                                 // 1 = pairs int32, 0 = int64

// ---------------------------------------------------------------------------
// packed f32x2 helpers (Blackwell FFMA2 path)
// ---------------------------------------------------------------------------
__device__ __forceinline__ ull ffma2(ull a, ull b, ull c) {
    ull d;
    asm("fma.rn.f32x2 %0, %1, %2, %3;" : "=l"(d) : "l"(a), "l"(b), "l"(c));
    return d;
}
__device__ __forceinline__ ull pk2(float lo, float hi) {
    ull r;
    asm("mov.b64 %0, {%1, %2};" : "=l"(r) : "f"(lo), "f"(hi));
    return r;
}
__device__ __forceinline__ void unpk2(ull v, float& lo, float& hi) {
    asm("mov.b64 {%0, %1}, %2;" : "=f"(lo), "=f"(hi) : "l"(v));
}

// ---------------------------------------------------------------------------
// Kernel A (grid 130 x 256): partials of (W2 @ W1) with deep-MLP float4 loads.
//   blocks 0..127: kt = b & 15 (k-tile of 128 floats = 32 float4),
//                  jt = b >> 4  (j-tile of 128 rows). Warp owns 16 rows.
//                  Per thread: 16 float4 W1 loads (2 batches of 8 in flight).
//   block 128: cvec = W2@b1 + b2.   block 129: pairs-dtype detect.
// ---------------------------------------------------------------------------
__global__ __launch_bounds__(256) void kA(const float* __restrict__ W1,
                                          const float* __restrict__ W2,
                                          const float* __restrict__ b1,
                                          const float* __restrict__ b2,
                                          const int* __restrict__ pairs_i32) {
    __shared__ ull    W2p[1024];   // (s,s) pairs of W2[c][jb+jj]   (8 KB)
    __shared__ float4 red[2048];   // cross-warp reduction scratch (32 KB)
    const int tid = threadIdx.x;
    const int b   = blockIdx.x;

    if (b >= 128) {
        if (b == 128) {            // cvec block
            int c = tid >> 5, lane = tid & 31;
            float s = 0.f;
            for (int j = lane; j < OBJ_DIM; j += 32)
                s += W2[c * OBJ_DIM + j] * b1[j];
            #pragma unroll
            for (int o = 16; o; o >>= 1) s += __shfl_xor_sync(0xffffffffu, s, o);
            if (lane == 0) g_cvec[c] = s + b2[c];
        } else if (tid < 32) {     // detect block: odd words zero under int64
            int v = pairs_i32[2 * tid + 1] | pairs_i32[2 * (tid + 32) + 1];
            #pragma unroll
            for (int o = 16; o; o >>= 1) v |= __shfl_xor_sync(0xffffffffu, v, o);
            if (tid == 0) g_fmt = (v != 0) ? 1 : 0;
        }
        return;
    }

    const int kt   = b & 15;
    const int jt   = b >> 4;           // 0..7
    const int jb   = jt * 128;
    const int warp = tid >> 5, lane = tid & 31;
    const int k4   = kt * 32 + lane;   // float4 column index in [0,512)

    // stage W2 pairs: W2p[c*128+jj] = (s,s), s = W2[c][jb+jj]
    for (int i = tid; i < 1024; i += 256) {
        float s = W2[(i >> 7) * OBJ_DIM + jb + (i & 127)];
        W2p[i] = pk2(s, s);
    }
    __syncthreads();

    const float4* W1v = reinterpret_cast<const float4*>(W1);  // row stride 512
    const int rowbase = jb + warp * 16;

    ull accA[8], accB[8];
    #pragma unroll
    for (int c = 0; c < 8; ++c) { accA[c] = 0ull; accB[c] = 0ull; }

    #pragma unroll
    for (int g = 0; g < 2; ++g) {
        float4 v[8];                                   // 8 LDG.128 in flight
        #pragma unroll
        for (int i = 0; i < 8; ++i)
            v[i] = W1v[(rowbase + g * 8 + i) * 512 + k4];
        #pragma unroll
        for (int i = 0; i < 8; ++i) {
            const int jj = warp * 16 + g * 8 + i;
            ull vA = pk2(v[i].x, v[i].y);
            ull vB = pk2(v[i].z, v[i].w);
            #pragma unroll
            for (int c = 0; c < 8; ++c) {
                ull ss = W2p[c * 128 + jj];            // LDS.64 broadcast
                accA[c] = ffma2(vA, ss, accA[c]);
                accB[c] = ffma2(vB, ss, accB[c]);
            }
        }
    }

    // cross-warp reduction over the 8 warps' j-subranges
    #pragma unroll
    for (int c = 0; c < 8; ++c) {
        float l0, h0, l1, h1;
        unpk2(accA[c], l0, h0);
        unpk2(accB[c], l1, h1);
        red[warp * 256 + c * 32 + lane] = make_float4(l0, h0, l1, h1);
    }
    __syncthreads();
    {
        float4 s = red[tid];
        #pragma unroll
        for (int w = 1; w < 8; ++w) {
            float4 t4 = red[w * 256 + tid];
            s.x += t4.x; s.y += t4.y; s.z += t4.z; s.w += t4.w;
        }
        int c     = tid >> 5, lanek = tid & 31;
        int c16   = ((kt >> 3) << 3) + c;              // half select + c
        int kloc4 = (kt & 7) * 32 + lanek;             // float4 idx within half
        reinterpret_cast<float4*>(g_Mp)[jt * 4096 + c16 * 256 + kloc4] = s;
    }
}

// ---------------------------------------------------------------------------
// Kernel R: reduce 8 j-partials -> g_M. Grid 16 x 256 (one float4 per thread).
// ---------------------------------------------------------------------------
__global__ __launch_bounds__(256) void kR() {
    const int t = blockIdx.x * 256 + threadIdx.x;      // 0..4095
    const float4* p4 = reinterpret_cast<const float4*>(g_Mp);
    float4 s = p4[t];
    #pragma unroll
    for (int j = 1; j < 8; ++j) {
        float4 a = p4[j * 4096 + t];
        s.x += a.x; s.y += a.y; s.z += a.z; s.w += a.w;
    }
    reinterpret_cast<float4*>(g_M)[t] = s;
}

// ---------------------------------------------------------------------------
// Kernel B: P[row][c16] = obj_feats[row] . M[c16]   (+ cvec on obj half)
// Grid: 128 blocks x 256 threads (8 warps). Warp owns 4 rows; lane owns k%32.
// Dynamic smem: max(16*1024, 512*33) floats = 67584 B -> request 69632.
// ---------------------------------------------------------------------------
extern __shared__ float s_dyn[];

__global__ __launch_bounds__(256, 1) void kB(const float* __restrict__ obj) {
    float* Ms = s_dyn;
    const int tid = threadIdx.x;

    // stage M (64 KB) in smem
    {
        float4*       d4 = reinterpret_cast<float4*>(Ms);
        const float4* s4 = reinterpret_cast<const float4*>(g_M);
        for (int i = tid; i < 4096; i += 256) d4[i] = s4[i];
    }
    __syncthreads();

    const int warp = tid >> 5, lane = tid & 31;
    const int row0 = blockIdx.x * 32 + warp * 4;
    const float4* objv = reinterpret_cast<const float4*>(obj);
    const float4* Ms4  = reinterpret_cast<const float4*>(Ms);

    ull acc[4][16];
    #pragma unroll
    for (int r = 0; r < 4; ++r)
        #pragma unroll
        for (int c = 0; c < 16; ++c) acc[r][c] = 0ull;   // bits 0 == {0.f,0.f}

    #pragma unroll
    for (int i = 0; i < 8; ++i) {
        const int k4 = lane + 32 * i;                    // float4 index, coalesced
        ull ovp[4][2];
        #pragma unroll
        for (int r = 0; r < 4; ++r) {
            float4 ov = objv[(row0 + r) * 256 + k4];
            ovp[r][0] = pk2(ov.x, ov.y);
            ovp[r][1] = pk2(ov.z, ov.w);
        }
        #pragma unroll
        for (int c = 0; c < 16; ++c) {
            float4 m = Ms4[c * 256 + k4];                // conflict-free LDS.128
            ull m0 = pk2(m.x, m.y), m1 = pk2(m.z, m.w);
            #pragma unroll
            for (int r = 0; r < 4; ++r) {
                acc[r][c] = ffma2(ovp[r][0], m0, acc[r][c]);
                acc[r][c] = ffma2(ovp[r][1], m1, acc[r][c]);
            }
        }
    }

    __syncthreads();   // everyone done reading Ms; reuse smem (stride-33 scratch)
    float* red = s_dyn;
    #pragma unroll
    for (int idx = 0; idx < 64; ++idx) {
        int r = idx >> 4, c = idx & 15;
        float lo, hi;
        unpk2(acc[r][c], lo, hi);
        red[(warp * 64 + idx) * 33 + lane] = lo + hi;    // conflict-free STS
    }
    __syncthreads();

    // 512 outputs per block; stride-33 makes the 32-lane sum conflict-free
    for (int out = tid; out < 512; out += 256) {
        float s = 0.f;
        #pragma unroll
        for (int l = 0; l < 32; ++l) s += red[out * 33 + l];
        int c = out & 15;
        if (c >= 8) s += g_cvec[c - 8];                  // fold bias into obj half
        g_P[blockIdx.x * 512 + out] = s;                 // == g_P[row*16 + c16]
    }
}

// ---------------------------------------------------------------------------
// Kernel C v5: float2-granular tasks. 262144 tasks == 262144 threads
// (grid 1024 x 256, ~57 warps/SM). Task t: pair p = t>>2, quarter q = t&3
// (2 output columns). 4 consecutive threads share one pair word (L1 dedup);
// per thread: two 8-byte L2 gathers from the 256 KB P table + one coalesced
// 8-byte store. Bounds: out float2 idx max 262143 -> 524288 floats exactly.
// Format-adaptive pair decode, index-masked (crash-proof).
// ---------------------------------------------------------------------------
__global__ __launch_bounds__(256) void kC(const void* __restrict__ pairs,
                                          float* __restrict__ out) {
    const int t = blockIdx.x * 256 + threadIdx.x;   // 0..262143
    const int p = t >> 2;                           // pair id, 0..65535
    const int q = t & 3;                            // column pair, 0..3

    int s, o;
    if (g_fmt) {                                          // int32 pairs
        int2 a = reinterpret_cast<const int2*>(pairs)[p];
        s = a.x; o = a.y;
    } else {                                              // int64 pairs
        longlong2 a = reinterpret_cast<const longlong2*>(pairs)[p];
        s = (int)a.x; o = (int)a.y;
    }
    s &= (N_OBJ - 1);
    o &= (N_OBJ - 1);                                     // no-op when valid

    // g_P as float2[]: row = 8 float2 (16 floats). sub cols 2q,2q+1 at s*8+q;
    // obj cols at o*8+4+q (obj half includes cvec).
    const float2* P2 = reinterpret_cast<const float2*>(g_P);
    float2 A = __ldg(&P2[s * 8 + q]);
    float2 B = __ldg(&P2[o * 8 + 4 + q]);

    reinterpret_cast<float2*>(out)[t] = make_float2(A.x + B.x, A.y + B.y);
}

// ---------------------------------------------------------------------------
// Launch. Inputs bound BY ELEMENT COUNT (robust to metadata ordering):
//   obj_feats f32[4194304], pairs [131072 elems], W1 f32[2097152],
//   b1 f32[1024], W2 f32[8192], b2 f32[8].  Output: f32[524288].
// ---------------------------------------------------------------------------
extern "C" void kernel_launch(void* const* d_in, const int* in_sizes, int n_in,
                              void* d_out, int out_size) {
    (void)out_size;
    const float* obj   = nullptr;
    const void*  pairs = nullptr;
    const float* W1    = nullptr;
    const float* b1    = nullptr;
    const float* W2    = nullptr;
    const float* b2    = nullptr;

    for (int i = 0; i < n_in; ++i) {
        switch (in_sizes[i]) {
            case N_OBJ * OBJ_DIM:       obj   = (const float*)d_in[i]; break; // 4194304
            case N_PAIRS * 2:           pairs = d_in[i];               break; // 131072
            case OBJ_DIM * 2 * OBJ_DIM: W1    = (const float*)d_in[i]; break; // 2097152
            case OBJ_DIM:               b1    = (const float*)d_in[i]; break; // 1024
            case 8 * OBJ_DIM:           W2    = (const float*)d_in[i]; break; // 8192
            case 8:                     b2    = (const float*)d_in[i]; break; // 8
            default: break;
        }
    }
    float* out = (float*)d_out;

    // Idempotent, called every time (no static guards); not stream-ordered.
    cudaFuncSetAttribute(kB, cudaFuncAttributeMaxDynamicSharedMemorySize, 69632);

    kA<<<130, 256>>>(W1, W2, b1, b2, (const int*)pairs);
    kR<<<16, 256>>>();
    kB<<<128, 256, 69632>>>(obj);
    kC<<<1024, 256>>>(pairs, out);
}